// round 13
// baseline (speedup 1.0000x reference)
#include <cuda_runtime.h>
#include <cuda_fp16.h>
#include <cstdint>

// Problem constants
#define BB 64
#define CC 64
#define TT 2000
#define PL 200
#define STRD 100
#define EE 512
#define PP 19
#define NROWS (BB*CC*PP)   // 77824
#define EPSV 1e-5f

// GEMM tiling: 64M x 128N per CTA, 8 warps of 32x32, fp16 k16 MMA
#define BM 64
#define BN 128
#define KSTG 32        // floats per stage = 2 kg of 16
#define NSTAGE 7       // 224 padded K (13 real kg)
#define EPI_PITCH 132  // padded fp32 row pitch for epilogue staging

#define STATS_BLOCKS (NROWS / 8)   // 9728

// Scratch
__device__ float g_mean[NROWS];
__device__ float g_inv[NROWS];
__device__ float g_wsum[EE];
__device__ float g_pe2[PP * EE];   // bias[d] + pos[p][d]

// ---------------- prep: wsum + pe2 fused ----------------
__global__ void prep_kernel(const float* __restrict__ W,
                            const float* __restrict__ bias,
                            const float* __restrict__ pos) {
    int b = blockIdx.x;
    if (b < 38) {                      // pe2: 38*256 = 9728 = PP*EE
        int i = b * 256 + threadIdx.x;
        g_pe2[i] = pos[i] + bias[i & (EE - 1)];
    } else {                           // wsum: 2*256 = 512
        int d = (b - 38) * 256 + threadIdx.x;
        const float* wr = W + (size_t)d * PL;
        float s = 0.f;
        #pragma unroll 8
        for (int l = 0; l < PL; ++l) s += wr[l];
        g_wsum[d] = s;
    }
}

// ---------------- JAX threefry2x32, partitionable mode ----------------
__device__ __forceinline__ void threefry(uint32_t k0, uint32_t k1,
                                         uint32_t x0, uint32_t x1,
                                         uint32_t& o0, uint32_t& o1) {
    uint32_t ks2 = k0 ^ k1 ^ 0x1BD11BDAu;
    x0 += k0; x1 += k1;
#define TF_RND(r) { x0 += x1; x1 = (x1 << r) | (x1 >> (32 - r)); x1 ^= x0; }
    TF_RND(13) TF_RND(15) TF_RND(26) TF_RND(6)  x0 += k1;  x1 += ks2 + 1u;
    TF_RND(17) TF_RND(29) TF_RND(16) TF_RND(24) x0 += ks2; x1 += k0 + 2u;
    TF_RND(13) TF_RND(15) TF_RND(26) TF_RND(6)  x0 += k0;  x1 += k1 + 3u;
    TF_RND(17) TF_RND(29) TF_RND(16) TF_RND(24) x0 += k1;  x1 += ks2 + 4u;
    TF_RND(13) TF_RND(15) TF_RND(26) TF_RND(6)  x0 += ks2; x1 += k0 + 5u;
#undef TF_RND
    o0 = x0; o1 = x1;
}

__device__ __forceinline__ uint32_t prf32(uint32_t k0, uint32_t k1, uint32_t i) {
    uint32_t o0, o1;
    threefry(k0, k1, 0u, i, o0, o1);
    return o0 ^ o1;
}

__device__ __forceinline__ float u01(uint32_t bits) {
    return __uint_as_float((bits >> 9) | 0x3f800000u) - 1.0f;
}

__device__ void mask_row(int row, float* __restrict__ mout) {
    uint32_t k1a, k1b, k2a, k2b;
    threefry(0u, 42u, 0u, 0u, k1a, k1b);
    threefry(0u, 42u, 0u, 1u, k2a, k2b);

    float r0 = u01(prf32(k2a, k2b, (uint32_t)(row * 3 + 0)));
    float r1 = u01(prf32(k2a, k2b, (uint32_t)(row * 3 + 1)));
    float r2 = u01(prf32(k2a, k2b, (uint32_t)(row * 3 + 2)));

    bool m[PP];
    #pragma unroll
    for (int j = 0; j < PP; ++j)
        m[j] = u01(prf32(k1a, k1b, (uint32_t)(row * PP + j))) < 0.1f;

    if (r0 < 0.5f)  { for (int j = PP - 1; j >= 1; --j) m[j] = m[j] | m[j - 1]; }
    if (r1 < 0.5f)  { for (int j = 0; j < PP - 1; ++j) m[j] = m[j] | m[j + 1]; }
    if (r2 < 0.25f) { for (int j = 0; j < PP - 1; ++j) m[j] = m[j] | m[j + 1]; }

    float* dst = mout + (size_t)row * PP;
    #pragma unroll
    for (int j = 0; j < PP; ++j) dst[j] = m[j] ? 1.0f : 0.0f;
}

// ---------------- stats + patches copy (+ mask blocks folded in) ----------------
__global__ void stats_kernel(const float* __restrict__ x,
                             float* __restrict__ patches,
                             float* __restrict__ mean_out,
                             float* __restrict__ std_out,
                             float* __restrict__ mout) {
    if (blockIdx.x >= STATS_BLOCKS) {
        int row = (blockIdx.x - STATS_BLOCKS) * 256 + threadIdx.x;
        if (row < BB * CC) mask_row(row, mout);
        return;
    }
    int warp = (blockIdx.x * blockDim.x + threadIdx.x) >> 5;
    int lane = threadIdx.x & 31;
    int bc = warp / PP;
    int p  = warp % PP;
    const float* src = x + (size_t)bc * TT + p * STRD;
    float* dst = patches + (size_t)warp * PL;

    float s = 0.f, s2 = 0.f;
    #pragma unroll
    for (int i = 0; i < 7; ++i) {
        int l = lane + i * 32;
        if (l < PL) {
            float v = src[l];
            s += v; s2 += v * v;
            dst[l] = v;
        }
    }
    #pragma unroll
    for (int off = 16; off; off >>= 1) {
        s  += __shfl_xor_sync(0xffffffffu, s,  off);
        s2 += __shfl_xor_sync(0xffffffffu, s2, off);
    }
    if (lane == 0) {
        float mean = s * (1.f / PL);
        float var  = (s2 - s * mean) * (1.f / (PL - 1));
        float sd   = sqrtf(fmaxf(var, 0.f));
        mean_out[warp] = mean;
        std_out[warp]  = sd;
        g_mean[warp] = mean;
        g_inv[warp]  = 1.f / (sd + EPSV);
    }
}

// ---------------- fp16 mma helpers ----------------
__device__ __forceinline__ uint32_t packh2(float lo, float hi) {
    __half2 h = __floats2half2_rn(lo, hi);
    return *(uint32_t*)&h;
}

__device__ __forceinline__ void mma_f16_k16(float* d, const uint32_t* a,
                                            const uint32_t* b, const float* c) {
    asm volatile(
        "mma.sync.aligned.m16n8k16.row.col.f32.f16.f16.f32 "
        "{%0,%1,%2,%3}, {%4,%5,%6,%7}, {%8,%9}, {%10,%11,%12,%13};\n"
        : "=f"(d[0]), "=f"(d[1]), "=f"(d[2]), "=f"(d[3])
        : "r"(a[0]), "r"(a[1]), "r"(a[2]), "r"(a[3]),
          "r"(b[0]), "r"(b[1]),
          "f"(c[0]), "f"(c[1]), "f"(c[2]), "f"(c[3]));
}

// ---------------- GEMM ----------------
// smem (u32): smA [buf(2)][kg(2)][row(64)][8]  = 2048 u32
//             smB [buf(2)][kg(2)][row(128)][8] = 4096 u32
// kg word layout per row: even words = (h0h1)(h2h3)(h4h5)(h6h7) at w0,w2,w4,w6
//                         odd  words = (h8h9)(h10h11)(h12h13)(h14h15) at w1,w3,w5,w7
__global__ __launch_bounds__(256, 3) void gemm_tc_kernel(
    const float* __restrict__ x, const float* __restrict__ W,
    const int* __restrict__ subj, const float* __restrict__ gain,
    float* __restrict__ emb)
{
    extern __shared__ uint32_t sm[];
    uint32_t* smA = sm;           // 2048 u32
    uint32_t* smB = sm + 2048;    // 4096 u32
    float* epi = (float*)sm;      // 64 x 132 fp32 (reused after mainloop)

    const int tid  = threadIdx.x;
    const int wid  = tid >> 5;
    const int lane = tid & 31;
    const int g    = lane >> 2;   // 0..7
    const int tg   = lane & 3;    // 0..3
    const int wm   = wid >> 2;    // 0..1 : 32-row warp tile
    const int wn   = wid & 3;     // 0..3 : 32-col warp tile

    const int row0 = blockIdx.x * BM;
    const int n0   = blockIdx.y * BN;

    // A loader: 4 threads/row: arow=tid>>2, q=tid&3 covers floats [q*8, q*8+8)
    const int arow = tid >> 2;      // 0..63
    const int q    = tid & 3;
    const int akofs = q * 8;
    // chunk word targets (k = q*8 and q*8+4)
    const int kgj0 = (q * 8) >> 4;
    const int koj0 = (q * 8) & 15;
    const int wj0  = (koj0 < 8) ? koj0 : (koj0 - 7);
    const int kgj1 = (q * 8 + 4) >> 4;
    const int koj1 = (q * 8 + 4) & 15;
    const int wj1  = (koj1 < 8) ? koj1 : (koj1 - 7);

    const float* srcA;
    {
        int ar = row0 + arow;
        srcA = x + (size_t)(ar / PP) * TT + (ar % PP) * STRD + akofs;
    }

    // B loader: 2 threads/row: brow=tid>>1, bkg=tid&1 covers one kg (16 floats)
    const int brow = tid >> 1;      // 0..127
    const int bkg  = tid & 1;
    const int bkofs = bkg * 16;
    const float* srcB = W + (size_t)(n0 + brow) * PL + bkofs;

    float acc[2][4][4];
    #pragma unroll
    for (int mt = 0; mt < 2; ++mt)
        #pragma unroll
        for (int nt = 0; nt < 4; ++nt)
            #pragma unroll
            for (int qq = 0; qq < 4; ++qq) acc[mt][nt][qq] = 0.f;

    // packed prefetch regs
    uint32_t ua[4];   // A: 2 chunks x 2 words
    uint32_t ub[8];   // B: one kg, pair order (h0h1)..(h14h15)

    // prefetch stage 0 (all k < 200 at s=0 except none; akofs<=24, bkofs<=16)
    {
        float4 a0 = *(const float4*)(srcA);
        float4 a1 = *(const float4*)(srcA + 4);
        ua[0] = packh2(a0.x, a0.y); ua[1] = packh2(a0.z, a0.w);
        ua[2] = packh2(a1.x, a1.y); ua[3] = packh2(a1.z, a1.w);
        #pragma unroll
        for (int j = 0; j < 4; ++j) {
            float4 b = *(const float4*)(srcB + j * 4);
            ub[j * 2 + 0] = packh2(b.x, b.y);
            ub[j * 2 + 1] = packh2(b.z, b.w);
        }
    }

    #pragma unroll 1
    for (int s = 0; s < NSTAGE; ++s) {
        const int bufA = (s & 1) * 1024;
        const int bufB = (s & 1) * 2048;
        // store current stage
        {
            uint32_t* da0 = smA + bufA + kgj0 * 512 + arow * 8 + wj0;
            uint32_t* da1 = smA + bufA + kgj1 * 512 + arow * 8 + wj1;
            da0[0] = ua[0]; da0[2] = ua[1];
            da1[0] = ua[2]; da1[2] = ua[3];
            uint32_t* db = smB + bufB + bkg * 1024 + brow * 8;
            *(uint4*)(db)     = make_uint4(ub[0], ub[4], ub[1], ub[5]);
            *(uint4*)(db + 4) = make_uint4(ub[2], ub[6], ub[3], ub[7]);
        }
        __syncthreads();

        // prefetch next stage (packed immediately)
        if (s + 1 < NSTAGE) {
            const int rel = (s + 1) * KSTG;
            {
                bool ok0 = (rel + akofs)     < PL;
                bool ok1 = (rel + akofs + 4) < PL;
                float4 a0 = ok0 ? *(const float4*)(srcA + rel)     : make_float4(0,0,0,0);
                float4 a1 = ok1 ? *(const float4*)(srcA + rel + 4) : make_float4(0,0,0,0);
                ua[0] = packh2(a0.x, a0.y); ua[1] = packh2(a0.z, a0.w);
                ua[2] = packh2(a1.x, a1.y); ua[3] = packh2(a1.z, a1.w);
            }
            #pragma unroll
            for (int j = 0; j < 4; ++j) {
                bool ok = (rel + bkofs + j * 4) < PL;
                float4 b = ok ? *(const float4*)(srcB + rel + j * 4) : make_float4(0,0,0,0);
                ub[j * 2 + 0] = packh2(b.x, b.y);
                ub[j * 2 + 1] = packh2(b.z, b.w);
            }
        }

        // compute: kg pair (skip all-zero kg 13 at s==6)
        #pragma unroll
        for (int kg = 0; kg < 2; ++kg) {
            if (s == NSTAGE - 1 && kg == 1) break;
            const uint32_t* ab = smA + bufA + kg * 512;
            const uint32_t* bb = smB + bufB + kg * 1024;
            uint32_t af[2][4];
            #pragma unroll
            for (int mt = 0; mt < 2; ++mt) {
                int m = wm * 32 + mt * 16 + g;
                uint2 lo = *(const uint2*)(ab + m * 8 + tg * 2);
                uint2 hi = *(const uint2*)(ab + (m + 8) * 8 + tg * 2);
                af[mt][0] = lo.x; af[mt][1] = hi.x;
                af[mt][2] = lo.y; af[mt][3] = hi.y;
            }
            uint32_t bf[4][2];
            #pragma unroll
            for (int nt = 0; nt < 4; ++nt) {
                int n = wn * 32 + nt * 8 + g;
                uint2 bv = *(const uint2*)(bb + n * 8 + tg * 2);
                bf[nt][0] = bv.x; bf[nt][1] = bv.y;
            }
            #pragma unroll
            for (int mt = 0; mt < 2; ++mt)
                #pragma unroll
                for (int nt = 0; nt < 4; ++nt)
                    mma_f16_k16(acc[mt][nt], af[mt], bf[nt], acc[mt][nt]);
        }
        __syncthreads();
    }

    // ---- staged epilogue ----
    // 1) raw accumulators -> padded smem tile
    {
        const int dloc = wn * 32 + 2 * tg;
        #pragma unroll
        for (int mt = 0; mt < 2; ++mt) {
            #pragma unroll
            for (int h = 0; h < 2; ++h) {
                int rloc = wm * 32 + mt * 16 + g + h * 8;
                float* erow = epi + rloc * EPI_PITCH + dloc;
                #pragma unroll
                for (int nt = 0; nt < 4; ++nt)
                    *(float2*)(erow + nt * 8) =
                        make_float2(acc[mt][nt][h * 2 + 0], acc[mt][nt][h * 2 + 1]);
            }
        }
    }
    __syncthreads();

    // 2) coalesced fused copy-out
    #pragma unroll 1
    for (int it = 0; it < 8; ++it) {
        int fid = it * 256 + tid;
        int row = fid >> 5;            // 0..63
        int c4  = (fid & 31) * 4;      // 0..124
        int r   = row0 + row;
        float mv = g_mean[r], iv = g_inv[r];
        float miv = mv * iv;
        int rp  = r % PP;
        int sid = subj[(r / PP) >> 6];
        int d   = n0 + c4;

        float4 a  = *(float4*)&epi[row * EPI_PITCH + c4];
        float4 w4 = *(const float4*)&g_wsum[d];
        float4 p4 = *(const float4*)&g_pe2[rp * EE + d];
        float4 g4 = *(const float4*)&gain[(size_t)sid * EE + d];
        float4 o;
        o.x = (iv * a.x - miv * w4.x + p4.x) * g4.x;
        o.y = (iv * a.y - miv * w4.y + p4.y) * g4.y;
        o.z = (iv * a.z - miv * w4.z + p4.z) * g4.z;
        o.w = (iv * a.w - miv * w4.w + p4.w) * g4.w;
        *(float4*)&emb[(size_t)r * EE + d] = o;
    }
}

// ---------------- launch ----------------
extern "C" void kernel_launch(void* const* d_in, const int* in_sizes, int n_in,
                              void* d_out, int out_size) {
    const float* x    = (const float*)d_in[0];
    const int*   subj = (const int*)  d_in[1];
    const float* W    = (const float*)d_in[2];
    const float* bias = (const float*)d_in[3];
    const float* pos  = (const float*)d_in[4];
    const float* gain = (const float*)d_in[5];

    float* out      = (float*)d_out;
    float* emb      = out;                               // 77824*512
    float* patches  = emb + (size_t)NROWS * EE;          // 77824*200
    float* mfloat   = patches + (size_t)NROWS * PL;      // 77824
    float* mean_out = mfloat + NROWS;                    // 77824
    float* std_out  = mean_out + NROWS;                  // 77824

    const int smem_bytes = BM * EPI_PITCH * 4;           // 33792 (mainloop uses 24576)
    cudaFuncSetAttribute(gemm_tc_kernel,
                         cudaFuncAttributeMaxDynamicSharedMemorySize, smem_bytes);

    prep_kernel<<<40, 256>>>(W, bias, pos);
    stats_kernel<<<STATS_BLOCKS + 16, 256>>>(x, patches, mean_out, std_out, mfloat);
    dim3 g(NROWS / BM, EE / BN);
    gemm_tc_kernel<<<g, 256, smem_bytes>>>(x, W, subj, gain, emb);
}

// round 14
// speedup vs baseline: 1.2045x; 1.2045x over previous
#include <cuda_runtime.h>
#include <cuda_fp16.h>
#include <cstdint>

// Problem constants
#define BB 64
#define CC 64
#define TT 2000
#define PL 200
#define STRD 100
#define EE 512
#define PP 19
#define NROWS (BB*CC*PP)   // 77824
#define EPSV 1e-5f

// GEMM tiling: 128M x 128N per CTA, 16 warps of 32x32, fp16 k16 MMA
#define BM 128
#define BN 128
#define KSTG 32        // floats per stage = 2 kg of 16
#define NSTAGE 7       // 224 padded K (13 real kg)
#define EPI_PITCH 132  // padded fp32 row pitch for epilogue staging

// fused prologue block ranges
#define STATS_BLOCKS (NROWS / 8)            // 9728
#define MASK_BLOCKS  16
#define PE2_BLOCKS   38                     // 38*256 = PP*EE
#define WSUM_BLOCKS  64                     // 64 blocks x 8 warps = 512 rows

// Scratch
__device__ float g_mean[NROWS];
__device__ float g_inv[NROWS];
__device__ float g_wsum[EE];
__device__ float g_pe2[PP * EE];   // bias[d] + pos[p][d]

// ---------------- JAX threefry2x32, partitionable mode ----------------
__device__ __forceinline__ void threefry(uint32_t k0, uint32_t k1,
                                         uint32_t x0, uint32_t x1,
                                         uint32_t& o0, uint32_t& o1) {
    uint32_t ks2 = k0 ^ k1 ^ 0x1BD11BDAu;
    x0 += k0; x1 += k1;
#define TF_RND(r) { x0 += x1; x1 = (x1 << r) | (x1 >> (32 - r)); x1 ^= x0; }
    TF_RND(13) TF_RND(15) TF_RND(26) TF_RND(6)  x0 += k1;  x1 += ks2 + 1u;
    TF_RND(17) TF_RND(29) TF_RND(16) TF_RND(24) x0 += ks2; x1 += k0 + 2u;
    TF_RND(13) TF_RND(15) TF_RND(26) TF_RND(6)  x0 += k0;  x1 += k1 + 3u;
    TF_RND(17) TF_RND(29) TF_RND(16) TF_RND(24) x0 += k1;  x1 += ks2 + 4u;
    TF_RND(13) TF_RND(15) TF_RND(26) TF_RND(6)  x0 += ks2; x1 += k0 + 5u;
#undef TF_RND
    o0 = x0; o1 = x1;
}

__device__ __forceinline__ uint32_t prf32(uint32_t k0, uint32_t k1, uint32_t i) {
    uint32_t o0, o1;
    threefry(k0, k1, 0u, i, o0, o1);
    return o0 ^ o1;
}

__device__ __forceinline__ float u01(uint32_t bits) {
    return __uint_as_float((bits >> 9) | 0x3f800000u) - 1.0f;
}

__device__ void mask_row(int row, float* __restrict__ mout) {
    uint32_t k1a, k1b, k2a, k2b;
    threefry(0u, 42u, 0u, 0u, k1a, k1b);
    threefry(0u, 42u, 0u, 1u, k2a, k2b);

    float r0 = u01(prf32(k2a, k2b, (uint32_t)(row * 3 + 0)));
    float r1 = u01(prf32(k2a, k2b, (uint32_t)(row * 3 + 1)));
    float r2 = u01(prf32(k2a, k2b, (uint32_t)(row * 3 + 2)));

    bool m[PP];
    #pragma unroll
    for (int j = 0; j < PP; ++j)
        m[j] = u01(prf32(k1a, k1b, (uint32_t)(row * PP + j))) < 0.1f;

    if (r0 < 0.5f)  { for (int j = PP - 1; j >= 1; --j) m[j] = m[j] | m[j - 1]; }
    if (r1 < 0.5f)  { for (int j = 0; j < PP - 1; ++j) m[j] = m[j] | m[j + 1]; }
    if (r2 < 0.25f) { for (int j = 0; j < PP - 1; ++j) m[j] = m[j] | m[j + 1]; }

    float* dst = mout + (size_t)row * PP;
    #pragma unroll
    for (int j = 0; j < PP; ++j) dst[j] = m[j] ? 1.0f : 0.0f;
}

// ---------------- fused prologue: stats + mask + pe2 + wsum ----------------
__global__ void prologue_kernel(const float* __restrict__ x,
                                const float* __restrict__ W,
                                const float* __restrict__ bias,
                                const float* __restrict__ pos,
                                float* __restrict__ patches,
                                float* __restrict__ mean_out,
                                float* __restrict__ std_out,
                                float* __restrict__ mout) {
    const int b = blockIdx.x;
    const int lane = threadIdx.x & 31;

    if (b < STATS_BLOCKS) {
        // stats + patches copy: warp per row
        int warp = (b * blockDim.x + threadIdx.x) >> 5;
        int bc = warp / PP;
        int p  = warp % PP;
        const float* src = x + (size_t)bc * TT + p * STRD;
        float* dst = patches + (size_t)warp * PL;

        float s = 0.f, s2 = 0.f;
        #pragma unroll
        for (int i = 0; i < 7; ++i) {
            int l = lane + i * 32;
            if (l < PL) {
                float v = src[l];
                s += v; s2 += v * v;
                dst[l] = v;
            }
        }
        #pragma unroll
        for (int off = 16; off; off >>= 1) {
            s  += __shfl_xor_sync(0xffffffffu, s,  off);
            s2 += __shfl_xor_sync(0xffffffffu, s2, off);
        }
        if (lane == 0) {
            float mean = s * (1.f / PL);
            float var  = (s2 - s * mean) * (1.f / (PL - 1));
            float sd   = sqrtf(fmaxf(var, 0.f));
            mean_out[warp] = mean;
            std_out[warp]  = sd;
            g_mean[warp] = mean;
            g_inv[warp]  = 1.f / (sd + EPSV);
        }
        return;
    }
    if (b < STATS_BLOCKS + MASK_BLOCKS) {
        int row = (b - STATS_BLOCKS) * 256 + threadIdx.x;
        if (row < BB * CC) mask_row(row, mout);
        return;
    }
    if (b < STATS_BLOCKS + MASK_BLOCKS + PE2_BLOCKS) {
        int i = (b - STATS_BLOCKS - MASK_BLOCKS) * 256 + threadIdx.x;
        g_pe2[i] = pos[i] + bias[i & (EE - 1)];
        return;
    }
    // wsum: warp per W row
    {
        int warp = ((b - STATS_BLOCKS - MASK_BLOCKS - PE2_BLOCKS) * 256 + threadIdx.x) >> 5;
        if (warp >= EE) return;
        const float* wr = W + (size_t)warp * PL;
        float s = 0.f;
        #pragma unroll
        for (int i = 0; i < 7; ++i) {
            int l = lane + i * 32;
            if (l < PL) s += wr[l];
        }
        #pragma unroll
        for (int off = 16; off; off >>= 1)
            s += __shfl_xor_sync(0xffffffffu, s, off);
        if (lane == 0) g_wsum[warp] = s;
    }
}

// ---------------- fp16 mma helpers ----------------
__device__ __forceinline__ uint32_t packh2(float lo, float hi) {
    __half2 h = __floats2half2_rn(lo, hi);
    return *(uint32_t*)&h;
}

__device__ __forceinline__ void mma_f16_k16(float* d, const uint32_t* a,
                                            const uint32_t* b, const float* c) {
    asm volatile(
        "mma.sync.aligned.m16n8k16.row.col.f32.f16.f16.f32 "
        "{%0,%1,%2,%3}, {%4,%5,%6,%7}, {%8,%9}, {%10,%11,%12,%13};\n"
        : "=f"(d[0]), "=f"(d[1]), "=f"(d[2]), "=f"(d[3])
        : "r"(a[0]), "r"(a[1]), "r"(a[2]), "r"(a[3]),
          "r"(b[0]), "r"(b[1]),
          "f"(c[0]), "f"(c[1]), "f"(c[2]), "f"(c[3]));
}

// ---------------- GEMM (R12 structure) ----------------
// smem (u32), per matrix: [buf(2)][kg(2)][row(128)][8 words]
// kg word layout per row: even words = (h0,h1)(h2,h3)(h4,h5)(h6,h7) at w0,w2,w4,w6
//                         odd  words = (h8,h9)(h10,h11)(h12,h13)(h14,h15) at w1,w3,w5,w7
__global__ __launch_bounds__(512, 1) void gemm_tc_kernel(
    const float* __restrict__ x, const float* __restrict__ W,
    const int* __restrict__ subj, const float* __restrict__ gain,
    float* __restrict__ emb)
{
    extern __shared__ uint32_t sm[];
    uint32_t* smA = sm;           // 8192 u32 (2 buf x 2 kg x 128 x 8)
    uint32_t* smB = sm + 8192;    // 8192 u32
    float* epi = (float*)sm;      // 128 x 132 fp32 (reused after mainloop)

    const int tid  = threadIdx.x;
    const int wid  = tid >> 5;
    const int lane = tid & 31;
    const int g    = lane >> 2;   // 0..7
    const int tg   = lane & 3;    // 0..3
    const int wm   = wid >> 2;    // 0..3 : 32-row warp tile
    const int wn   = wid & 3;     // 0..3 : 32-col warp tile

    const int row0 = blockIdx.x * BM;
    const int n0   = blockIdx.y * BN;

    // loaders: 8 lanes per row x 16B -> warp covers 4 rows x 128B contiguous
    const int lrow8 = tid >> 3;    // 0..63 ; covers rows lrow8 and lrow8+64
    const int lq    = tid & 7;     // k float offset = lq*4
    const int kofs  = lq * 4;
    const int kg_l  = lq >> 2;                 // kg of this 4-float chunk
    const int ko    = (lq & 3) * 4;            // float offset within kg
    const int w0    = (ko < 8) ? ko : (ko - 7);  // first word index (pair-permuted)

    const float* srcA0;
    const float* srcA1;
    {
        int ar0 = row0 + lrow8;
        int ar1 = row0 + lrow8 + 64;
        srcA0 = x + (size_t)(ar0 / PP) * TT + (ar0 % PP) * STRD + kofs;
        srcA1 = x + (size_t)(ar1 / PP) * TT + (ar1 % PP) * STRD + kofs;
    }
    const float* srcB0 = W + (size_t)(n0 + lrow8) * PL + kofs;
    const float* srcB1 = W + (size_t)(n0 + lrow8 + 64) * PL + kofs;

    float acc[2][4][4];
    #pragma unroll
    for (int mt = 0; mt < 2; ++mt)
        #pragma unroll
        for (int nt = 0; nt < 4; ++nt)
            #pragma unroll
            for (int qq = 0; qq < 4; ++qq) acc[mt][nt][qq] = 0.f;

    float4 va0, va1, vb0, vb1;

    // prefetch stage 0
    va0 = *(const float4*)srcA0;
    va1 = *(const float4*)srcA1;
    vb0 = *(const float4*)srcB0;
    vb1 = *(const float4*)srcB1;

    #pragma unroll 1
    for (int s = 0; s < NSTAGE; ++s) {
        const int buf = (s & 1) * 4096;
        // store current stage: 2 STS.32 per (row, matrix)
        {
            uint32_t* da0 = smA + buf + kg_l * 1024 + lrow8 * 8 + w0;
            uint32_t* da1 = smA + buf + kg_l * 1024 + (lrow8 + 64) * 8 + w0;
            uint32_t* db0 = smB + buf + kg_l * 1024 + lrow8 * 8 + w0;
            uint32_t* db1 = smB + buf + kg_l * 1024 + (lrow8 + 64) * 8 + w0;
            da0[0] = packh2(va0.x, va0.y); da0[2] = packh2(va0.z, va0.w);
            da1[0] = packh2(va1.x, va1.y); da1[2] = packh2(va1.z, va1.w);
            db0[0] = packh2(vb0.x, vb0.y); db0[2] = packh2(vb0.z, vb0.w);
            db1[0] = packh2(vb1.x, vb1.y); db1[2] = packh2(vb1.z, vb1.w);
        }
        __syncthreads();

        // prefetch next stage
        if (s + 1 < NSTAGE) {
            const int rel = (s + 1) * KSTG;
            const bool ok = (rel + kofs) < PL;
            va0 = ok ? *(const float4*)(srcA0 + rel) : make_float4(0.f,0.f,0.f,0.f);
            va1 = ok ? *(const float4*)(srcA1 + rel) : make_float4(0.f,0.f,0.f,0.f);
            vb0 = ok ? *(const float4*)(srcB0 + rel) : make_float4(0.f,0.f,0.f,0.f);
            vb1 = ok ? *(const float4*)(srcB1 + rel) : make_float4(0.f,0.f,0.f,0.f);
        }

        // compute: kg pair (skip the all-zero kg 13 at s==6)
        #pragma unroll
        for (int kg = 0; kg < 2; ++kg) {
            if (s == NSTAGE - 1 && kg == 1) break;
            const uint32_t* ab = smA + buf + kg * 1024;
            const uint32_t* bb = smB + buf + kg * 1024;
            uint32_t af[2][4];
            #pragma unroll
            for (int mt = 0; mt < 2; ++mt) {
                int m = wm * 32 + mt * 16 + g;
                uint2 lo = *(const uint2*)(ab + m * 8 + tg * 2);
                uint2 hi = *(const uint2*)(ab + (m + 8) * 8 + tg * 2);
                af[mt][0] = lo.x; af[mt][1] = hi.x;
                af[mt][2] = lo.y; af[mt][3] = hi.y;
            }
            uint32_t bf[4][2];
            #pragma unroll
            for (int nt = 0; nt < 4; ++nt) {
                int n = wn * 32 + nt * 8 + g;
                uint2 bv = *(const uint2*)(bb + n * 8 + tg * 2);
                bf[nt][0] = bv.x; bf[nt][1] = bv.y;
            }
            #pragma unroll
            for (int mt = 0; mt < 2; ++mt)
                #pragma unroll
                for (int nt = 0; nt < 4; ++nt)
                    mma_f16_k16(acc[mt][nt], af[mt], bf[nt], acc[mt][nt]);
        }
        __syncthreads();
    }

    // ---- staged epilogue ----
    // 1) raw accumulators -> padded smem tile (conflict-free STS.64)
    {
        const int dloc = wn * 32 + 2 * tg;
        #pragma unroll
        for (int mt = 0; mt < 2; ++mt) {
            #pragma unroll
            for (int h = 0; h < 2; ++h) {
                int rloc = wm * 32 + mt * 16 + g + h * 8;
                float* erow = epi + rloc * EPI_PITCH + dloc;
                #pragma unroll
                for (int nt = 0; nt < 4; ++nt)
                    *(float2*)(erow + nt * 8) =
                        make_float2(acc[mt][nt][h * 2 + 0], acc[mt][nt][h * 2 + 1]);
            }
        }
    }
    __syncthreads();

    // 2) coalesced fused copy-out
    #pragma unroll 1
    for (int it = 0; it < 8; ++it) {
        int fid = it * 512 + tid;
        int row = fid >> 5;            // 0..127
        int c4  = (fid & 31) * 4;      // 0..124
        int r   = row0 + row;
        float mv = g_mean[r], iv = g_inv[r];
        float miv = mv * iv;
        int rp  = r % PP;
        int sid = subj[(r / PP) >> 6];
        int d   = n0 + c4;

        float4 a  = *(float4*)&epi[row * EPI_PITCH + c4];
        float4 w4 = *(const float4*)&g_wsum[d];
        float4 p4 = *(const float4*)&g_pe2[rp * EE + d];
        float4 g4 = *(const float4*)&gain[(size_t)sid * EE + d];
        float4 o;
        o.x = (iv * a.x - miv * w4.x + p4.x) * g4.x;
        o.y = (iv * a.y - miv * w4.y + p4.y) * g4.y;
        o.z = (iv * a.z - miv * w4.z + p4.z) * g4.z;
        o.w = (iv * a.w - miv * w4.w + p4.w) * g4.w;
        *(float4*)&emb[(size_t)r * EE + d] = o;
    }
}

// ---------------- launch ----------------
extern "C" void kernel_launch(void* const* d_in, const int* in_sizes, int n_in,
                              void* d_out, int out_size) {
    const float* x    = (const float*)d_in[0];
    const int*   subj = (const int*)  d_in[1];
    const float* W    = (const float*)d_in[2];
    const float* bias = (const float*)d_in[3];
    const float* pos  = (const float*)d_in[4];
    const float* gain = (const float*)d_in[5];

    float* out      = (float*)d_out;
    float* emb      = out;                               // 77824*512
    float* patches  = emb + (size_t)NROWS * EE;          // 77824*200
    float* mfloat   = patches + (size_t)NROWS * PL;      // 77824
    float* mean_out = mfloat + NROWS;                    // 77824
    float* std_out  = mean_out + NROWS;                  // 77824

    const int smem_bytes = BM * EPI_PITCH * 4;           // 67584 > 65536 mainloop
    cudaFuncSetAttribute(gemm_tc_kernel,
                         cudaFuncAttributeMaxDynamicSharedMemorySize, smem_bytes);

    prologue_kernel<<<STATS_BLOCKS + MASK_BLOCKS + PE2_BLOCKS + WSUM_BLOCKS, 256>>>(
        x, W, bias, pos, patches, mean_out, std_out, mfloat);
    dim3 g(NROWS / BM, EE / BN);
    gemm_tc_kernel<<<g, 512, smem_bytes>>>(x, W, subj, gain, emb);
}

// round 15
// speedup vs baseline: 1.2732x; 1.0571x over previous
#include <cuda_runtime.h>
#include <cuda_fp16.h>
#include <cstdint>

// Problem constants
#define BB 64
#define CC 64
#define TT 2000
#define PL 200
#define STRD 100
#define EE 512
#define PP 19
#define NROWS (BB*CC*PP)   // 77824
#define EPSV 1e-5f

// GEMM tiling: 128M x 128N per CTA, 16 warps of 32x32, fp16 k16 MMA
#define BM 128
#define BN 128
#define KSTG 32        // floats per stage = 2 kg of 16
#define NSTAGE 7       // 224 padded K (13 real kg)
#define EPI_PITCH 132  // padded fp32 row pitch for epilogue staging

// fused prologue block ranges
#define STATS_BLOCKS (NROWS / 8)            // 9728
#define MASK_BLOCKS  16
#define PE2_BLOCKS   38                     // 38*256 = PP*EE
#define WSUM_BLOCKS  64                     // 64 blocks x 8 warps = 512 rows

// Scratch
__device__ float g_mean[NROWS];
__device__ float g_inv[NROWS];
__device__ float g_wsum[EE];
__device__ float g_pe2[PP * EE];   // bias[d] + pos[p][d]

// ---------------- JAX threefry2x32, partitionable mode ----------------
__device__ __forceinline__ void threefry(uint32_t k0, uint32_t k1,
                                         uint32_t x0, uint32_t x1,
                                         uint32_t& o0, uint32_t& o1) {
    uint32_t ks2 = k0 ^ k1 ^ 0x1BD11BDAu;
    x0 += k0; x1 += k1;
#define TF_RND(r) { x0 += x1; x1 = (x1 << r) | (x1 >> (32 - r)); x1 ^= x0; }
    TF_RND(13) TF_RND(15) TF_RND(26) TF_RND(6)  x0 += k1;  x1 += ks2 + 1u;
    TF_RND(17) TF_RND(29) TF_RND(16) TF_RND(24) x0 += ks2; x1 += k0 + 2u;
    TF_RND(13) TF_RND(15) TF_RND(26) TF_RND(6)  x0 += k0;  x1 += k1 + 3u;
    TF_RND(17) TF_RND(29) TF_RND(16) TF_RND(24) x0 += k1;  x1 += ks2 + 4u;
    TF_RND(13) TF_RND(15) TF_RND(26) TF_RND(6)  x0 += ks2; x1 += k0 + 5u;
#undef TF_RND
    o0 = x0; o1 = x1;
}

__device__ __forceinline__ uint32_t prf32(uint32_t k0, uint32_t k1, uint32_t i) {
    uint32_t o0, o1;
    threefry(k0, k1, 0u, i, o0, o1);
    return o0 ^ o1;
}

__device__ __forceinline__ float u01(uint32_t bits) {
    return __uint_as_float((bits >> 9) | 0x3f800000u) - 1.0f;
}

__device__ void mask_row(int row, float* __restrict__ mout) {
    uint32_t k1a, k1b, k2a, k2b;
    threefry(0u, 42u, 0u, 0u, k1a, k1b);
    threefry(0u, 42u, 0u, 1u, k2a, k2b);

    float r0 = u01(prf32(k2a, k2b, (uint32_t)(row * 3 + 0)));
    float r1 = u01(prf32(k2a, k2b, (uint32_t)(row * 3 + 1)));
    float r2 = u01(prf32(k2a, k2b, (uint32_t)(row * 3 + 2)));

    bool m[PP];
    #pragma unroll
    for (int j = 0; j < PP; ++j)
        m[j] = u01(prf32(k1a, k1b, (uint32_t)(row * PP + j))) < 0.1f;

    if (r0 < 0.5f)  { for (int j = PP - 1; j >= 1; --j) m[j] = m[j] | m[j - 1]; }
    if (r1 < 0.5f)  { for (int j = 0; j < PP - 1; ++j) m[j] = m[j] | m[j + 1]; }
    if (r2 < 0.25f) { for (int j = 0; j < PP - 1; ++j) m[j] = m[j] | m[j + 1]; }

    float* dst = mout + (size_t)row * PP;
    #pragma unroll
    for (int j = 0; j < PP; ++j) dst[j] = m[j] ? 1.0f : 0.0f;
}

// ---------------- fused prologue: stats + mask + pe2 + wsum ----------------
__global__ void prologue_kernel(const float* __restrict__ x,
                                const float* __restrict__ W,
                                const float* __restrict__ bias,
                                const float* __restrict__ pos,
                                float* __restrict__ patches,
                                float* __restrict__ mean_out,
                                float* __restrict__ std_out,
                                float* __restrict__ mout) {
    const int b = blockIdx.x;
    const int lane = threadIdx.x & 31;

    if (b < STATS_BLOCKS) {
        // stats + patches copy: warp per row
        int warp = (b * blockDim.x + threadIdx.x) >> 5;
        int bc = warp / PP;
        int p  = warp % PP;
        const float* src = x + (size_t)bc * TT + p * STRD;
        float* dst = patches + (size_t)warp * PL;

        float s = 0.f, s2 = 0.f;
        #pragma unroll
        for (int i = 0; i < 7; ++i) {
            int l = lane + i * 32;
            if (l < PL) {
                float v = src[l];
                s += v; s2 += v * v;
                dst[l] = v;
            }
        }
        #pragma unroll
        for (int off = 16; off; off >>= 1) {
            s  += __shfl_xor_sync(0xffffffffu, s,  off);
            s2 += __shfl_xor_sync(0xffffffffu, s2, off);
        }
        if (lane == 0) {
            float mean = s * (1.f / PL);
            float var  = (s2 - s * mean) * (1.f / (PL - 1));
            float sd   = sqrtf(fmaxf(var, 0.f));
            mean_out[warp] = mean;
            std_out[warp]  = sd;
            g_mean[warp] = mean;
            g_inv[warp]  = 1.f / (sd + EPSV);
        }
        return;
    }
    if (b < STATS_BLOCKS + MASK_BLOCKS) {
        int row = (b - STATS_BLOCKS) * 256 + threadIdx.x;
        if (row < BB * CC) mask_row(row, mout);
        return;
    }
    if (b < STATS_BLOCKS + MASK_BLOCKS + PE2_BLOCKS) {
        int i = (b - STATS_BLOCKS - MASK_BLOCKS) * 256 + threadIdx.x;
        g_pe2[i] = pos[i] + bias[i & (EE - 1)];
        return;
    }
    // wsum: warp per W row
    {
        int warp = ((b - STATS_BLOCKS - MASK_BLOCKS - PE2_BLOCKS) * 256 + threadIdx.x) >> 5;
        if (warp >= EE) return;
        const float* wr = W + (size_t)warp * PL;
        float s = 0.f;
        #pragma unroll
        for (int i = 0; i < 7; ++i) {
            int l = lane + i * 32;
            if (l < PL) s += wr[l];
        }
        #pragma unroll
        for (int off = 16; off; off >>= 1)
            s += __shfl_xor_sync(0xffffffffu, s, off);
        if (lane == 0) g_wsum[warp] = s;
    }
}

// ---------------- fp16 mma helpers ----------------
__device__ __forceinline__ uint32_t packh2(float lo, float hi) {
    __half2 h = __floats2half2_rn(lo, hi);
    return *(uint32_t*)&h;
}

__device__ __forceinline__ void mma_f16_k16(float* d, const uint32_t* a,
                                            const uint32_t* b, const float* c) {
    asm volatile(
        "mma.sync.aligned.m16n8k16.row.col.f32.f16.f16.f32 "
        "{%0,%1,%2,%3}, {%4,%5,%6,%7}, {%8,%9}, {%10,%11,%12,%13};\n"
        : "=f"(d[0]), "=f"(d[1]), "=f"(d[2]), "=f"(d[3])
        : "r"(a[0]), "r"(a[1]), "r"(a[2]), "r"(a[3]),
          "r"(b[0]), "r"(b[1]),
          "f"(c[0]), "f"(c[1]), "f"(c[2]), "f"(c[3]));
}

// ---------------- GEMM ----------------
// smem (u32), per matrix: [buf(2)][kg(2)][row(128)][8 words]
// kg word layout per row: even words = (h0,h1)(h2,h3)(h4,h5)(h6,h7) at w0,w2,w4,w6
//                         odd  words = (h8,h9)(h10,h11)(h12,h13)(h14,h15) at w1,w3,w5,w7
// One barrier per stage: compute(s) reads buf[s&1]; the next write to that
// buffer is store(s+2), reachable only after SYNC(s+1) which orders it after
// every warp's compute(s).
__global__ __launch_bounds__(512, 1) void gemm_tc_kernel(
    const float* __restrict__ x, const float* __restrict__ W,
    const int* __restrict__ subj, const float* __restrict__ gain,
    float* __restrict__ emb)
{
    extern __shared__ uint32_t sm[];
    uint32_t* smA = sm;           // 8192 u32 (2 buf x 2 kg x 128 x 8)
    uint32_t* smB = sm + 8192;    // 8192 u32
    float* epi = (float*)sm;      // 128 x 132 fp32 (reused after mainloop)

    const int tid  = threadIdx.x;
    const int wid  = tid >> 5;
    const int lane = tid & 31;
    const int g    = lane >> 2;   // 0..7
    const int tg   = lane & 3;    // 0..3
    const int wm   = wid >> 2;    // 0..3 : 32-row warp tile
    const int wn   = wid & 3;     // 0..3 : 32-col warp tile

    const int row0 = blockIdx.x * BM;
    const int n0   = blockIdx.y * BN;

    // loaders: 8 lanes per row x 16B -> warp covers 4 rows x 128B contiguous
    const int lrow8 = tid >> 3;    // 0..63 ; covers rows lrow8 and lrow8+64
    const int lq    = tid & 7;     // k float offset = lq*4
    const int kofs  = lq * 4;
    const int kg_l  = lq >> 2;                 // kg of this 4-float chunk
    const int ko    = (lq & 3) * 4;            // float offset within kg
    const int w0    = (ko < 8) ? ko : (ko - 7);  // first word index (pair-permuted)

    const float* srcA0;
    const float* srcA1;
    {
        int ar0 = row0 + lrow8;
        int ar1 = row0 + lrow8 + 64;
        srcA0 = x + (size_t)(ar0 / PP) * TT + (ar0 % PP) * STRD + kofs;
        srcA1 = x + (size_t)(ar1 / PP) * TT + (ar1 % PP) * STRD + kofs;
    }
    const float* srcB0 = W + (size_t)(n0 + lrow8) * PL + kofs;
    const float* srcB1 = W + (size_t)(n0 + lrow8 + 64) * PL + kofs;

    float acc[2][4][4];
    #pragma unroll
    for (int mt = 0; mt < 2; ++mt)
        #pragma unroll
        for (int nt = 0; nt < 4; ++nt)
            #pragma unroll
            for (int qq = 0; qq < 4; ++qq) acc[mt][nt][qq] = 0.f;

    // two prefetch register sets (2 stages in flight)
    float4 ca0, ca1, cb0, cb1;   // current (to be stored this stage)
    float4 na0, na1, nb0, nb1;   // next

    // prefetch stage 0 and stage 1
    ca0 = *(const float4*)srcA0;
    ca1 = *(const float4*)srcA1;
    cb0 = *(const float4*)srcB0;
    cb1 = *(const float4*)srcB1;
    na0 = *(const float4*)(srcA0 + KSTG);
    na1 = *(const float4*)(srcA1 + KSTG);
    nb0 = *(const float4*)(srcB0 + KSTG);
    nb1 = *(const float4*)(srcB1 + KSTG);

    #pragma unroll 1
    for (int s = 0; s < NSTAGE; ++s) {
        const int buf = (s & 1) * 4096;
        // store current stage: 2 STS.32 per (row, matrix)
        {
            uint32_t* da0 = smA + buf + kg_l * 1024 + lrow8 * 8 + w0;
            uint32_t* da1 = smA + buf + kg_l * 1024 + (lrow8 + 64) * 8 + w0;
            uint32_t* db0 = smB + buf + kg_l * 1024 + lrow8 * 8 + w0;
            uint32_t* db1 = smB + buf + kg_l * 1024 + (lrow8 + 64) * 8 + w0;
            da0[0] = packh2(ca0.x, ca0.y); da0[2] = packh2(ca0.z, ca0.w);
            da1[0] = packh2(ca1.x, ca1.y); da1[2] = packh2(ca1.z, ca1.w);
            db0[0] = packh2(cb0.x, cb0.y); db0[2] = packh2(cb0.z, cb0.w);
            db1[0] = packh2(cb1.x, cb1.y); db1[2] = packh2(cb1.z, cb1.w);
        }
        __syncthreads();

        // rotate and prefetch stage s+2 (consumed 2 stages later)
        ca0 = na0; ca1 = na1; cb0 = nb0; cb1 = nb1;
        if (s + 2 < NSTAGE) {
            const int rel = (s + 2) * KSTG;
            const bool ok = (rel + kofs) < PL;
            na0 = ok ? *(const float4*)(srcA0 + rel) : make_float4(0.f,0.f,0.f,0.f);
            na1 = ok ? *(const float4*)(srcA1 + rel) : make_float4(0.f,0.f,0.f,0.f);
            nb0 = ok ? *(const float4*)(srcB0 + rel) : make_float4(0.f,0.f,0.f,0.f);
            nb1 = ok ? *(const float4*)(srcB1 + rel) : make_float4(0.f,0.f,0.f,0.f);
        }

        // compute: kg pair (skip the all-zero kg 13 at s==6)
        #pragma unroll
        for (int kg = 0; kg < 2; ++kg) {
            if (s == NSTAGE - 1 && kg == 1) break;
            const uint32_t* ab = smA + buf + kg * 1024;
            const uint32_t* bb = smB + buf + kg * 1024;
            uint32_t af[2][4];
            #pragma unroll
            for (int mt = 0; mt < 2; ++mt) {
                int m = wm * 32 + mt * 16 + g;
                uint2 lo = *(const uint2*)(ab + m * 8 + tg * 2);
                uint2 hi = *(const uint2*)(ab + (m + 8) * 8 + tg * 2);
                af[mt][0] = lo.x; af[mt][1] = hi.x;
                af[mt][2] = lo.y; af[mt][3] = hi.y;
            }
            uint32_t bf[4][2];
            #pragma unroll
            for (int nt = 0; nt < 4; ++nt) {
                int n = wn * 32 + nt * 8 + g;
                uint2 bv = *(const uint2*)(bb + n * 8 + tg * 2);
                bf[nt][0] = bv.x; bf[nt][1] = bv.y;
            }
            #pragma unroll
            for (int mt = 0; mt < 2; ++mt)
                #pragma unroll
                for (int nt = 0; nt < 4; ++nt)
                    mma_f16_k16(acc[mt][nt], af[mt], bf[nt], acc[mt][nt]);
        }
        // no second barrier: double buffering + SYNC(s+1) orders store(s+2)
        // after every warp's compute(s).
    }
    __syncthreads();   // protect smem reuse (epi staging) against final compute

    // ---- staged epilogue ----
    // 1) raw accumulators -> padded smem tile (conflict-free STS.64)
    {
        const int dloc = wn * 32 + 2 * tg;
        #pragma unroll
        for (int mt = 0; mt < 2; ++mt) {
            #pragma unroll
            for (int h = 0; h < 2; ++h) {
                int rloc = wm * 32 + mt * 16 + g + h * 8;
                float* erow = epi + rloc * EPI_PITCH + dloc;
                #pragma unroll
                for (int nt = 0; nt < 4; ++nt)
                    *(float2*)(erow + nt * 8) =
                        make_float2(acc[mt][nt][h * 2 + 0], acc[mt][nt][h * 2 + 1]);
            }
        }
    }
    __syncthreads();

    // 2) coalesced fused copy-out (fully unrolled -> batched independent LDGs)
    #pragma unroll
    for (int it = 0; it < 8; ++it) {
        int fid = it * 512 + tid;
        int row = fid >> 5;            // 0..127
        int c4  = (fid & 31) * 4;      // 0..124
        int r   = row0 + row;
        float mv = g_mean[r], iv = g_inv[r];
        float miv = mv * iv;
        int rp  = r % PP;
        int sid = subj[(r / PP) >> 6];
        int d   = n0 + c4;

        float4 a  = *(float4*)&epi[row * EPI_PITCH + c4];
        float4 w4 = *(const float4*)&g_wsum[d];
        float4 p4 = *(const float4*)&g_pe2[rp * EE + d];
        float4 g4 = *(const float4*)&gain[(size_t)sid * EE + d];
        float4 o;
        o.x = (iv * a.x - miv * w4.x + p4.x) * g4.x;
        o.y = (iv * a.y - miv * w4.y + p4.y) * g4.y;
        o.z = (iv * a.z - miv * w4.z + p4.z) * g4.z;
        o.w = (iv * a.w - miv * w4.w + p4.w) * g4.w;
        *(float4*)&emb[(size_t)r * EE + d] = o;
    }
}

// ---------------- launch ----------------
extern "C" void kernel_launch(void* const* d_in, const int* in_sizes, int n_in,
                              void* d_out, int out_size) {
    const float* x    = (const float*)d_in[0];
    const int*   subj = (const int*)  d_in[1];
    const float* W    = (const float*)d_in[2];
    const float* bias = (const float*)d_in[3];
    const float* pos  = (const float*)d_in[4];
    const float* gain = (const float*)d_in[5];

    float* out      = (float*)d_out;
    float* emb      = out;                               // 77824*512
    float* patches  = emb + (size_t)NROWS * EE;          // 77824*200
    float* mfloat   = patches + (size_t)NROWS * PL;      // 77824
    float* mean_out = mfloat + NROWS;                    // 77824
    float* std_out  = mean_out + NROWS;                  // 77824

    const int smem_bytes = BM * EPI_PITCH * 4;           // 67584 > 65536 mainloop
    cudaFuncSetAttribute(gemm_tc_kernel,
                         cudaFuncAttributeMaxDynamicSharedMemorySize, smem_bytes);

    prologue_kernel<<<STATS_BLOCKS + MASK_BLOCKS + PE2_BLOCKS + WSUM_BLOCKS, 256>>>(
        x, W, bias, pos, patches, mean_out, std_out, mfloat);
    dim3 g(NROWS / BM, EE / BN);
    gemm_tc_kernel<<<g, 512, smem_bytes>>>(x, W, subj, gain, emb);
}